// round 5
// baseline (speedup 1.0000x reference)
#include <cuda_runtime.h>

#define B_ 2
#define N_ 4096
#define C_ 512
#define H_ 8
#define D_ 64
#define SCALE_ 0.125f
#define LOG2E_ 1.4426950408889634f

#define LDP_ 40   // proj smem stride (words), ==8 mod 32
#define LDA_ 72   // attn smem stride (words), ==8 mod 32

// Scratch (allocation-free rule: __device__ globals)
__device__ float g_Q[B_*H_*N_*D_];
__device__ float g_K[B_*H_*N_*D_];
__device__ float g_V[B_*H_*N_*D_];
__device__ float g_X[B_*N_*C_];

// ---------------------------------------------------------------------------
__device__ __forceinline__ unsigned f2tf(float x) {
    unsigned r;
    asm("cvt.rna.tf32.f32 %0, %1;" : "=r"(r) : "f"(x));
    return r;
}
__device__ __forceinline__ float ex2(float x) {
    float r;
    asm("ex2.approx.ftz.f32 %0, %1;" : "=f"(r) : "f"(x));
    return r;
}
__device__ __forceinline__ void mma8(float* d, const unsigned* a, const unsigned* b) {
    asm volatile(
        "mma.sync.aligned.m16n8k8.row.col.f32.tf32.tf32.f32 "
        "{%0,%1,%2,%3},{%4,%5,%6,%7},{%8,%9},{%0,%1,%2,%3};"
        : "+f"(d[0]), "+f"(d[1]), "+f"(d[2]), "+f"(d[3])
        : "r"(a[0]), "r"(a[1]), "r"(a[2]), "r"(a[3]), "r"(b[0]), "r"(b[1]));
}

// Fragment-pair interleave within an 8-word group: c -> 2*(c&3) + (c>>2).
// Pair (c, c+4) for c<4 lands at (2c, 2c+1): one LDS.64 per fragment pair.

// ---------------------------------------------------------------------------
// QKV projection: Out(r,c) = sum_k A(r,k) * W(c,k). CTA = 128 rows x 64 cols
// (one head). 8 warps, warp = 16x64. k-slab prefetch into registers.
// ---------------------------------------------------------------------------
__global__ __launch_bounds__(256) void proj_qkv_kernel(
    const float* __restrict__ qin, const float* __restrict__ kin,
    const float* __restrict__ vin, const float* __restrict__ Wq,
    const float* __restrict__ Wk,  const float* __restrict__ Wv)
{
    const int which = blockIdx.z;
    const float* A = (which == 0) ? qin : (which == 1) ? kin : vin;
    const float* W = (which == 0) ? Wq  : (which == 1) ? Wk  : Wv;
    float* Out     = (which == 0) ? g_Q : (which == 1) ? g_K : g_V;

    const int r0 = blockIdx.y * 128;
    const int hx = blockIdx.x;

    __shared__ unsigned Asu[128 * LDP_];
    __shared__ unsigned Wsu[64 * LDP_];

    const int tid  = threadIdx.x;
    const int warp = tid >> 5;
    const int lane = tid & 31;
    const int qr = lane >> 2, qc = lane & 3;

    float acc[8][4];
    #pragma unroll
    for (int nt = 0; nt < 8; nt++)
        #pragma unroll
        for (int j = 0; j < 4; j++) acc[nt][j] = 0.f;

    float4 ast[4], wst[2];
    // prologue: load slab 0
    #pragma unroll
    for (int i = 0; i < 4; i++) {
        int idx = tid + i * 256;
        ast[i] = *(const float4*)&A[(r0 + (idx >> 3)) * C_ + ((idx & 7) << 2)];
    }
    #pragma unroll
    for (int i = 0; i < 2; i++) {
        int idx = tid + i * 256;
        wst[i] = *(const float4*)&W[(hx * 64 + (idx >> 3)) * C_ + ((idx & 7) << 2)];
    }

    for (int k0 = 0; k0 < C_; k0 += 32) {
        __syncthreads();
        // store current slab (interleaved)
        #pragma unroll
        for (int i = 0; i < 4; i++) {
            int idx = tid + i * 256;
            int row = idx >> 3, kq = (idx & 7) << 2;
            int base = row * LDP_ + (kq & ~7) + ((kq >> 2) & 1);
            Asu[base + 0] = f2tf(ast[i].x);
            Asu[base + 2] = f2tf(ast[i].y);
            Asu[base + 4] = f2tf(ast[i].z);
            Asu[base + 6] = f2tf(ast[i].w);
        }
        #pragma unroll
        for (int i = 0; i < 2; i++) {
            int idx = tid + i * 256;
            int row = idx >> 3, kq = (idx & 7) << 2;
            int base = row * LDP_ + (kq & ~7) + ((kq >> 2) & 1);
            Wsu[base + 0] = f2tf(wst[i].x);
            Wsu[base + 2] = f2tf(wst[i].y);
            Wsu[base + 4] = f2tf(wst[i].z);
            Wsu[base + 6] = f2tf(wst[i].w);
        }
        // prefetch next slab
        if (k0 + 32 < C_) {
            #pragma unroll
            for (int i = 0; i < 4; i++) {
                int idx = tid + i * 256;
                ast[i] = *(const float4*)&A[(r0 + (idx >> 3)) * C_ + k0 + 32 + ((idx & 7) << 2)];
            }
            #pragma unroll
            for (int i = 0; i < 2; i++) {
                int idx = tid + i * 256;
                wst[i] = *(const float4*)&W[(hx * 64 + (idx >> 3)) * C_ + k0 + 32 + ((idx & 7) << 2)];
            }
        }
        __syncthreads();

        const int ar = warp * 16 + qr;
        #pragma unroll
        for (int ks = 0; ks < 4; ks++) {
            uint2 a01 = *(const uint2*)&Asu[ar * LDP_ + ks * 8 + 2 * qc];
            uint2 a23 = *(const uint2*)&Asu[(ar + 8) * LDP_ + ks * 8 + 2 * qc];
            unsigned a[4] = {a01.x, a23.x, a01.y, a23.y};
            #pragma unroll
            for (int nt = 0; nt < 8; nt++) {
                uint2 b = *(const uint2*)&Wsu[(nt * 8 + qr) * LDP_ + ks * 8 + 2 * qc];
                mma8(acc[nt], a, (const unsigned*)&b);
            }
        }
    }

    const int row0 = r0 + warp * 16 + qr;
    const int row1 = row0 + 8;
    const int b0g = row0 >> 12, n0g = row0 & (N_ - 1);
    const int b1g = row1 >> 12, n1g = row1 & (N_ - 1);
    float* O0 = &Out[(((b0g * H_ + hx) * N_) + n0g) * D_];
    float* O1 = &Out[(((b1g * H_ + hx) * N_) + n1g) * D_];
    #pragma unroll
    for (int nt = 0; nt < 8; nt++) {
        int col = nt * 8 + 2 * qc;
        *(float2*)&O0[col] = make_float2(acc[nt][0], acc[nt][1]);
        *(float2*)&O1[col] = make_float2(acc[nt][2], acc[nt][3]);
    }
}

// ---------------------------------------------------------------------------
// Flash attention, tensor cores, double-buffered K/V tiles.
// smem: [Kt0][Vt0][Kt1][Vt1][Ps], each K/V 64 x LDA_, Ps 128 x LDA_.
// ---------------------------------------------------------------------------
__global__ __launch_bounds__(256, 2) void attn_kernel()
{
    extern __shared__ unsigned sm[];
    unsigned* Ps = sm + 4 * 64 * LDA_;

    const int bh = blockIdx.y;
    const float* Qp = g_Q + bh * (N_ * D_);
    const float* Kp = g_K + bh * (N_ * D_);
    const float* Vp = g_V + bh * (N_ * D_);
    const int n0 = blockIdx.x * 128;

    const int tid  = threadIdx.x;
    const int warp = tid >> 5;
    const int lane = tid & 31;
    const int qr = lane >> 2, qc = lane & 3;

    // staging coordinates for this thread (4 float4 of K + 4 of V per tile)
    int skv[4], sdq[4];
    #pragma unroll
    for (int i = 0; i < 4; i++) {
        int e = tid + i * 256;
        skv[i] = e >> 4;
        sdq[i] = (e & 15) << 2;
    }

    float4 kst[4], vst[4];
    // prologue: load tile 0
    #pragma unroll
    for (int i = 0; i < 4; i++) {
        kst[i] = *(const float4*)&Kp[skv[i] * D_ + sdq[i]];
        vst[i] = *(const float4*)&Vp[skv[i] * D_ + sdq[i]];
    }

    // Q fragments, pre-scaled into log2 domain
    unsigned qa[8][4];
    {
        const float sc = SCALE_ * LOG2E_;
        const float* Q0 = &Qp[(n0 + warp * 16 + qr) * D_];
        const float* Q1 = Q0 + 8 * D_;
        #pragma unroll
        for (int ks = 0; ks < 8; ks++) {
            qa[ks][0] = f2tf(Q0[ks * 8 + qc] * sc);
            qa[ks][1] = f2tf(Q1[ks * 8 + qc] * sc);
            qa[ks][2] = f2tf(Q0[ks * 8 + qc + 4] * sc);
            qa[ks][3] = f2tf(Q1[ks * 8 + qc + 4] * sc);
        }
    }

    float o[8][4];
    #pragma unroll
    for (int nt = 0; nt < 8; nt++)
        #pragma unroll
        for (int j = 0; j < 4; j++) o[nt][j] = 0.f;
    float mrow[2] = {-1e30f, -1e30f};
    float lrow[2] = {0.f, 0.f};

    // store tile 0 into buffer 0
    {
        unsigned* Kt = sm;
        unsigned* Vt = sm + 64 * LDA_;
        #pragma unroll
        for (int i = 0; i < 4; i++) {
            int kb = skv[i] * LDA_ + (sdq[i] & ~7) + ((sdq[i] >> 2) & 1);
            Kt[kb + 0] = f2tf(kst[i].x);
            Kt[kb + 2] = f2tf(kst[i].y);
            Kt[kb + 4] = f2tf(kst[i].z);
            Kt[kb + 6] = f2tf(kst[i].w);
            int cv = (skv[i] & ~7) + ((skv[i] & 3) * 2) + ((skv[i] >> 2) & 1);
            Vt[(sdq[i] + 0) * LDA_ + cv] = f2tf(vst[i].x);
            Vt[(sdq[i] + 1) * LDA_ + cv] = f2tf(vst[i].y);
            Vt[(sdq[i] + 2) * LDA_ + cv] = f2tf(vst[i].z);
            Vt[(sdq[i] + 3) * LDA_ + cv] = f2tf(vst[i].w);
        }
    }
    __syncthreads();

    const int ar = warp * 16 + qr;
    const int NT = N_ / 64;

    for (int t = 0; t < NT; t++) {
        const int cur = t & 1;
        unsigned* Kt = sm + cur * (2 * 64 * LDA_);
        unsigned* Vt = Kt + 64 * LDA_;

        // S = Q K^T (log2 domain)
        float s[8][4];
        #pragma unroll
        for (int nt = 0; nt < 8; nt++)
            #pragma unroll
            for (int j = 0; j < 4; j++) s[nt][j] = 0.f;
        #pragma unroll
        for (int ks = 0; ks < 8; ks++) {
            #pragma unroll
            for (int nt = 0; nt < 8; nt++) {
                uint2 b = *(const uint2*)&Kt[(nt * 8 + qr) * LDA_ + ks * 8 + 2 * qc];
                mma8(s[nt], qa[ks], (const unsigned*)&b);
            }
        }

        // online softmax (base-2)
        #pragma unroll
        for (int i = 0; i < 2; i++) {
            float mx = -1e30f;
            #pragma unroll
            for (int nt = 0; nt < 8; nt++)
                mx = fmaxf(mx, fmaxf(s[nt][2 * i], s[nt][2 * i + 1]));
            mx = fmaxf(mx, __shfl_xor_sync(0xffffffffu, mx, 1));
            mx = fmaxf(mx, __shfl_xor_sync(0xffffffffu, mx, 2));
            float mn = fmaxf(mrow[i], mx);
            float alpha = ex2(mrow[i] - mn);
            mrow[i] = mn;
            float rs = 0.f;
            #pragma unroll
            for (int nt = 0; nt < 8; nt++) {
                s[nt][2 * i]     = ex2(s[nt][2 * i] - mn);
                s[nt][2 * i + 1] = ex2(s[nt][2 * i + 1] - mn);
                rs += s[nt][2 * i] + s[nt][2 * i + 1];
            }
            rs += __shfl_xor_sync(0xffffffffu, rs, 1);
            rs += __shfl_xor_sync(0xffffffffu, rs, 2);
            lrow[i] = lrow[i] * alpha + rs;
            #pragma unroll
            for (int nt = 0; nt < 8; nt++) {
                o[nt][2 * i]     *= alpha;
                o[nt][2 * i + 1] *= alpha;
            }
        }

        // store P (interleaved): col 2qc -> off n0p, col 2qc+1 -> n0p+2
        {
            const int n0p = ((2 * qc) & 3) * 2 + (qc >> 1);
            #pragma unroll
            for (int nt = 0; nt < 8; nt++) {
                int b0 = ar * LDA_ + nt * 8 + n0p;
                Ps[b0]     = f2tf(s[nt][0]);
                Ps[b0 + 2] = f2tf(s[nt][1]);
                int b1 = (ar + 8) * LDA_ + nt * 8 + n0p;
                Ps[b1]     = f2tf(s[nt][2]);
                Ps[b1 + 2] = f2tf(s[nt][3]);
            }
        }
        __syncwarp();

        // prefetch next K/V tile (consumed after the barrier below)
        if (t + 1 < NT) {
            const float* Kn = &Kp[(t + 1) * 64 * D_];
            const float* Vn = &Vp[(t + 1) * 64 * D_];
            #pragma unroll
            for (int i = 0; i < 4; i++) {
                kst[i] = *(const float4*)&Kn[skv[i] * D_ + sdq[i]];
                vst[i] = *(const float4*)&Vn[skv[i] * D_ + sdq[i]];
            }
        }

        // O += P V
        #pragma unroll
        for (int ks = 0; ks < 8; ks++) {
            uint2 a01 = *(const uint2*)&Ps[ar * LDA_ + ks * 8 + 2 * qc];
            uint2 a23 = *(const uint2*)&Ps[(ar + 8) * LDA_ + ks * 8 + 2 * qc];
            unsigned a[4] = {a01.x, a23.x, a01.y, a23.y};
            #pragma unroll
            for (int nt = 0; nt < 8; nt++) {
                uint2 b = *(const uint2*)&Vt[(nt * 8 + qr) * LDA_ + ks * 8 + 2 * qc];
                mma8(o[nt], a, (const unsigned*)&b);
            }
        }

        __syncthreads();   // all reads of buf[cur] done
        if (t + 1 < NT) {
            unsigned* Ktn = sm + ((t + 1) & 1) * (2 * 64 * LDA_);
            unsigned* Vtn = Ktn + 64 * LDA_;
            #pragma unroll
            for (int i = 0; i < 4; i++) {
                int kb = skv[i] * LDA_ + (sdq[i] & ~7) + ((sdq[i] >> 2) & 1);
                Ktn[kb + 0] = f2tf(kst[i].x);
                Ktn[kb + 2] = f2tf(kst[i].y);
                Ktn[kb + 4] = f2tf(kst[i].z);
                Ktn[kb + 6] = f2tf(kst[i].w);
                int cv = (skv[i] & ~7) + ((skv[i] & 3) * 2) + ((skv[i] >> 2) & 1);
                Vtn[(sdq[i] + 0) * LDA_ + cv] = f2tf(vst[i].x);
                Vtn[(sdq[i] + 1) * LDA_ + cv] = f2tf(vst[i].y);
                Vtn[(sdq[i] + 2) * LDA_ + cv] = f2tf(vst[i].z);
                Vtn[(sdq[i] + 3) * LDA_ + cv] = f2tf(vst[i].w);
            }
        }
        __syncthreads();   // new buffer visible
    }

    // epilogue
    const int bg = bh >> 3, hg = bh & 7;
    const float inv0 = 1.f / lrow[0];
    const float inv1 = 1.f / lrow[1];
    const int row0 = n0 + warp * 16 + qr;
    const int row1 = row0 + 8;
    float* X0 = &g_X[(bg * N_ + row0) * C_ + hg * D_];
    float* X1 = &g_X[(bg * N_ + row1) * C_ + hg * D_];
    #pragma unroll
    for (int nt = 0; nt < 8; nt++) {
        int col = nt * 8 + 2 * qc;
        *(float2*)&X0[col] = make_float2(o[nt][0] * inv0, o[nt][1] * inv0);
        *(float2*)&X1[col] = make_float2(o[nt][2] * inv1, o[nt][3] * inv1);
    }
}

// ---------------------------------------------------------------------------
// Output projection: out = X @ Wp^T + bp.
// ---------------------------------------------------------------------------
__global__ __launch_bounds__(256) void proj_out_kernel(
    const float* __restrict__ Wp, const float* __restrict__ bp,
    float* __restrict__ out)
{
    const int r0 = blockIdx.y * 128;
    const int cb = blockIdx.x * 64;

    __shared__ unsigned Asu[128 * LDP_];
    __shared__ unsigned Wsu[64 * LDP_];

    const int tid  = threadIdx.x;
    const int warp = tid >> 5;
    const int lane = tid & 31;
    const int qr = lane >> 2, qc = lane & 3;

    float acc[8][4];
    #pragma unroll
    for (int nt = 0; nt < 8; nt++)
        #pragma unroll
        for (int j = 0; j < 4; j++) acc[nt][j] = 0.f;

    float4 ast[4], wst[2];
    #pragma unroll
    for (int i = 0; i < 4; i++) {
        int idx = tid + i * 256;
        ast[i] = *(const float4*)&g_X[(r0 + (idx >> 3)) * C_ + ((idx & 7) << 2)];
    }
    #pragma unroll
    for (int i = 0; i < 2; i++) {
        int idx = tid + i * 256;
        wst[i] = *(const float4*)&Wp[(cb + (idx >> 3)) * C_ + ((idx & 7) << 2)];
    }

    for (int k0 = 0; k0 < C_; k0 += 32) {
        __syncthreads();
        #pragma unroll
        for (int i = 0; i < 4; i++) {
            int idx = tid + i * 256;
            int row = idx >> 3, kq = (idx & 7) << 2;
            int base = row * LDP_ + (kq & ~7) + ((kq >> 2) & 1);
            Asu[base + 0] = f2tf(ast[i].x);
            Asu[base + 2] = f2tf(ast[i].y);
            Asu[base + 4] = f2tf(ast[i].z);
            Asu[base + 6] = f2tf(ast[i].w);
        }
        #pragma unroll
        for (int i = 0; i < 2; i++) {
            int idx = tid + i * 256;
            int row = idx >> 3, kq = (idx & 7) << 2;
            int base = row * LDP_ + (kq & ~7) + ((kq >> 2) & 1);
            Wsu[base + 0] = f2tf(wst[i].x);
            Wsu[base + 2] = f2tf(wst[i].y);
            Wsu[base + 4] = f2tf(wst[i].z);
            Wsu[base + 6] = f2tf(wst[i].w);
        }
        if (k0 + 32 < C_) {
            #pragma unroll
            for (int i = 0; i < 4; i++) {
                int idx = tid + i * 256;
                ast[i] = *(const float4*)&g_X[(r0 + (idx >> 3)) * C_ + k0 + 32 + ((idx & 7) << 2)];
            }
            #pragma unroll
            for (int i = 0; i < 2; i++) {
                int idx = tid + i * 256;
                wst[i] = *(const float4*)&Wp[(cb + (idx >> 3)) * C_ + k0 + 32 + ((idx & 7) << 2)];
            }
        }
        __syncthreads();

        const int ar = warp * 16 + qr;
        #pragma unroll
        for (int ks = 0; ks < 4; ks++) {
            uint2 a01 = *(const uint2*)&Asu[ar * LDP_ + ks * 8 + 2 * qc];
            uint2 a23 = *(const uint2*)&Asu[(ar + 8) * LDP_ + ks * 8 + 2 * qc];
            unsigned a[4] = {a01.x, a23.x, a01.y, a23.y};
            #pragma unroll
            for (int nt = 0; nt < 8; nt++) {
                uint2 b = *(const uint2*)&Wsu[(nt * 8 + qr) * LDP_ + ks * 8 + 2 * qc];
                mma8(acc[nt], a, (const unsigned*)&b);
            }
        }
    }

    const int row0 = r0 + warp * 16 + qr;
    const int row1 = row0 + 8;
    #pragma unroll
    for (int nt = 0; nt < 8; nt++) {
        int col = cb + nt * 8 + 2 * qc;
        float b0v = bp[col], b1v = bp[col + 1];
        *(float2*)&out[row0 * C_ + col] =
            make_float2(acc[nt][0] + b0v, acc[nt][1] + b1v);
        *(float2*)&out[row1 * C_ + col] =
            make_float2(acc[nt][2] + b0v, acc[nt][3] + b1v);
    }
}

extern "C" void kernel_launch(void* const* d_in, const int* in_sizes, int n_in,
                              void* d_out, int out_size)
{
    const float* query = (const float*)d_in[0];
    const float* key   = (const float*)d_in[1];
    const float* value = (const float*)d_in[2];
    const float* Wq    = (const float*)d_in[3];
    const float* Wk    = (const float*)d_in[4];
    const float* Wv    = (const float*)d_in[5];
    const float* Wp    = (const float*)d_in[6];
    const float* bp    = (const float*)d_in[7];
    float* out = (float*)d_out;

    const int attn_smem = (4 * 64 + 128) * LDA_ * (int)sizeof(unsigned); // 110592
    cudaFuncSetAttribute(attn_kernel,
                         cudaFuncAttributeMaxDynamicSharedMemorySize, attn_smem);

    dim3 blk(256);
    proj_qkv_kernel<<<dim3(8, 64, 3), blk>>>(query, key, value, Wq, Wk, Wv);
    attn_kernel<<<dim3(32, 16), blk, attn_smem>>>();
    proj_out_kernel<<<dim3(8, 64), blk>>>(Wp, bp, out);
}

// round 6
// speedup vs baseline: 1.7678x; 1.7678x over previous
#include <cuda_runtime.h>

#define B_ 2
#define N_ 4096
#define C_ 512
#define H_ 8
#define D_ 64
#define SCALE_ 0.125f
#define LOG2E_ 1.4426950408889634f

#define LDP_ 36   // proj smem stride (words), ==4 mod 32 (ldmatrix conflict-free)
#define LDQ_ 68   // attn Q/K/P stride (words), ==4 mod 32
#define LDV_ 72   // attn V stride (words), ==8 mod 32 (scalar B-loads injective)

// Scratch (allocation-free rule: __device__ globals)
__device__ float g_Q[B_*H_*N_*D_];
__device__ float g_K[B_*H_*N_*D_];
__device__ float g_V[B_*H_*N_*D_];
__device__ float g_X[B_*N_*C_];

// ---------------------------------------------------------------------------
__device__ __forceinline__ unsigned f2tf(float x) {
    unsigned r;
    asm("cvt.rna.tf32.f32 %0, %1;" : "=r"(r) : "f"(x));
    return r;
}
__device__ __forceinline__ float ex2(float x) {
    float r;
    asm("ex2.approx.ftz.f32 %0, %1;" : "=f"(r) : "f"(x));
    return r;
}
__device__ __forceinline__ void mma8(float* d, const unsigned* a, const unsigned* b) {
    asm volatile(
        "mma.sync.aligned.m16n8k8.row.col.f32.tf32.tf32.f32 "
        "{%0,%1,%2,%3},{%4,%5,%6,%7},{%8,%9},{%0,%1,%2,%3};"
        : "+f"(d[0]), "+f"(d[1]), "+f"(d[2]), "+f"(d[3])
        : "r"(a[0]), "r"(a[1]), "r"(a[2]), "r"(a[3]), "r"(b[0]), "r"(b[1]));
}
__device__ __forceinline__ void ldsm4(unsigned* r, unsigned addr) {
    asm volatile(
        "ldmatrix.sync.aligned.m8n8.x4.shared.b16 {%0,%1,%2,%3}, [%4];"
        : "=r"(r[0]), "=r"(r[1]), "=r"(r[2]), "=r"(r[3]) : "r"(addr));
}
__device__ __forceinline__ unsigned su32(const void* p) {
    return (unsigned)__cvta_generic_to_shared(p);
}
__device__ __forceinline__ uint4 cvt4(float4 v) {
    return make_uint4(f2tf(v.x), f2tf(v.y), f2tf(v.z), f2tf(v.w));
}

// A-fragment ldmatrix lane geometry (m16k8 tf32 as 4 b16 8x8 matrices):
//   mats: (rows+0,k0)(rows+8,k0)(rows+0,k4)(rows+8,k4)
//   lane i -> row ((i>>3)&1)*8 + (i&7), k-chunk ((i>>4)&1)*4
// B-fragment x4 covers an nt-PAIR:
//   mats: (nt0,k0)(nt0,k4)(nt1,k0)(nt1,k4)
//   lane i -> row ((i>>4)&1)*8 + (i&7)  [within the pair], k-chunk ((i>>3)&1)*4

// ---------------------------------------------------------------------------
// QKV projection: Out(r,c) = sum_k A(r,k)*W(c,k). CTA = 128 rows x 64 cols
// (one head). 4 warps, each 32 rows x 64 cols (2 m16 blocks sharing B-frags).
// ---------------------------------------------------------------------------
__global__ __launch_bounds__(128, 3) void proj_qkv_kernel(
    const float* __restrict__ qin, const float* __restrict__ kin,
    const float* __restrict__ vin, const float* __restrict__ Wq,
    const float* __restrict__ Wk,  const float* __restrict__ Wv)
{
    const int which = blockIdx.z;
    const float* A = (which == 0) ? qin : (which == 1) ? kin : vin;
    const float* W = (which == 0) ? Wq  : (which == 1) ? Wk  : Wv;
    float* Out     = (which == 0) ? g_Q : (which == 1) ? g_K : g_V;

    const int r0 = blockIdx.y * 128;
    const int hx = blockIdx.x;

    __shared__ unsigned Asu[128 * LDP_];
    __shared__ unsigned Wsu[64 * LDP_];

    const int tid  = threadIdx.x;
    const int warp = tid >> 5;
    const int lane = tid & 31;
    const int qr = lane >> 2, qc = lane & 3;
    const int lrow = ((lane >> 3) & 1) * 8 + (lane & 7);
    const int lch  = ((lane >> 4) & 1) * 4;
    const int brow = ((lane >> 4) & 1) * 8 + (lane & 7);
    const int bch  = ((lane >> 3) & 1) * 4;

    const unsigned aAddr0 = su32(&Asu[(warp * 32 + lrow) * LDP_ + lch]);
    const unsigned aAddr1 = su32(&Asu[(warp * 32 + 16 + lrow) * LDP_ + lch]);
    const unsigned wAddr  = su32(&Wsu[brow * LDP_ + bch]);

    float acc[2][8][4];
    #pragma unroll
    for (int mb = 0; mb < 2; mb++)
        #pragma unroll
        for (int nt = 0; nt < 8; nt++)
            #pragma unroll
            for (int j = 0; j < 4; j++) acc[mb][nt][j] = 0.f;

    for (int k0 = 0; k0 < C_; k0 += 32) {
        // stage A (128x32) and W (64x32), tf32, contiguous STS.128
        #pragma unroll
        for (int i = 0; i < 8; i++) {
            int idx = tid + i * 128;
            int row = idx >> 3, kq = (idx & 7) << 2;
            float4 v = *(const float4*)&A[(r0 + row) * C_ + k0 + kq];
            *(uint4*)&Asu[row * LDP_ + kq] = cvt4(v);
        }
        #pragma unroll
        for (int i = 0; i < 4; i++) {
            int idx = tid + i * 128;
            int row = idx >> 3, kq = (idx & 7) << 2;
            float4 v = *(const float4*)&W[(hx * 64 + row) * C_ + k0 + kq];
            *(uint4*)&Wsu[row * LDP_ + kq] = cvt4(v);
        }
        __syncthreads();

        #pragma unroll
        for (int ks = 0; ks < 4; ks++) {
            unsigned a0[4], a1[4];
            ldsm4(a0, aAddr0 + ks * 32);
            ldsm4(a1, aAddr1 + ks * 32);
            #pragma unroll
            for (int p = 0; p < 4; p++) {
                unsigned b[4];
                ldsm4(b, wAddr + p * (16 * LDP_ * 4) + ks * 32);
                mma8(acc[0][2 * p],     a0, b);
                mma8(acc[0][2 * p + 1], a0, b + 2);
                mma8(acc[1][2 * p],     a1, b);
                mma8(acc[1][2 * p + 1], a1, b + 2);
            }
        }
        __syncthreads();
    }

    #pragma unroll
    for (int mb = 0; mb < 2; mb++) {
        int row0 = r0 + warp * 32 + mb * 16 + qr;
        int row1 = row0 + 8;
        int b0g = row0 >> 12, n0g = row0 & (N_ - 1);
        int b1g = row1 >> 12, n1g = row1 & (N_ - 1);
        float* O0 = &Out[(((b0g * H_ + hx) * N_) + n0g) * D_];
        float* O1 = &Out[(((b1g * H_ + hx) * N_) + n1g) * D_];
        #pragma unroll
        for (int nt = 0; nt < 8; nt++) {
            int col = nt * 8 + 2 * qc;
            *(float2*)&O0[col] = make_float2(acc[mb][nt][0], acc[mb][nt][1]);
            *(float2*)&O1[col] = make_float2(acc[mb][nt][2], acc[mb][nt][3]);
        }
    }
}

// ---------------------------------------------------------------------------
// Flash attention: CTA = 128 q-rows, 4 warps x 32 rows, KV tiles of 64.
// Q in smem (scaled, tf32) loaded once; K [kv][LDQ_], V row-major [kv][LDV_],
// P [128][LDQ_]. A/B fragments via ldmatrix; PV B via conflict-free LDS.32.
// ---------------------------------------------------------------------------
__global__ __launch_bounds__(128, 2) void attn_kernel()
{
    extern __shared__ unsigned sm[];
    unsigned* Qs = sm;                       // 128*LDQ_
    unsigned* Kt = Qs + 128 * LDQ_;          // 64*LDQ_
    unsigned* Vt = Kt + 64 * LDQ_;           // 64*LDV_
    unsigned* Ps = Vt + 64 * LDV_;           // 128*LDQ_

    const int bh = blockIdx.y;
    const float* Qp = g_Q + bh * (N_ * D_);
    const float* Kp = g_K + bh * (N_ * D_);
    const float* Vp = g_V + bh * (N_ * D_);
    const int n0 = blockIdx.x * 128;

    const int tid  = threadIdx.x;
    const int warp = tid >> 5;
    const int lane = tid & 31;
    const int qr = lane >> 2, qc = lane & 3;
    const int lrow = ((lane >> 3) & 1) * 8 + (lane & 7);
    const int lch  = ((lane >> 4) & 1) * 4;

    // Q -> smem, scaled into log2 domain, tf32
    {
        const float sc = SCALE_ * LOG2E_;
        #pragma unroll
        for (int i = 0; i < 16; i++) {
            int e = tid + i * 128;
            int row = e >> 4, dq = (e & 15) << 2;
            float4 v = *(const float4*)&Qp[(n0 + row) * D_ + dq];
            *(uint4*)&Qs[row * LDQ_ + dq] = make_uint4(
                f2tf(v.x * sc), f2tf(v.y * sc), f2tf(v.z * sc), f2tf(v.w * sc));
        }
    }

    const unsigned qAddr0 = su32(&Qs[(warp * 32 + lrow) * LDQ_ + lch]);
    const unsigned qAddr1 = su32(&Qs[(warp * 32 + 16 + lrow) * LDQ_ + lch]);
    const unsigned pAddr0 = su32(&Ps[(warp * 32 + lrow) * LDQ_ + lch]);
    const unsigned pAddr1 = su32(&Ps[(warp * 32 + 16 + lrow) * LDQ_ + lch]);
    const unsigned kAddr  = su32(
        &Kt[(((lane >> 4) & 1) * 8 + (lane & 7)) * LDQ_ + ((lane >> 3) & 1) * 4]);

    float o[2][8][4];
    #pragma unroll
    for (int mb = 0; mb < 2; mb++)
        #pragma unroll
        for (int nt = 0; nt < 8; nt++)
            #pragma unroll
            for (int j = 0; j < 4; j++) o[mb][nt][j] = 0.f;
    float mr[4] = {-1e30f, -1e30f, -1e30f, -1e30f};
    float lr[4] = {0.f, 0.f, 0.f, 0.f};

    for (int t = 0; t < N_ / 64; t++) {
        const float* Kb = Kp + t * 64 * D_;
        const float* Vb = Vp + t * 64 * D_;
        float4 kreg[8], vreg[8];
        #pragma unroll
        for (int i = 0; i < 8; i++) {
            int e = tid + i * 128;
            int off = (e >> 4) * D_ + ((e & 15) << 2);
            kreg[i] = *(const float4*)&Kb[off];
            vreg[i] = *(const float4*)&Vb[off];
        }
        __syncthreads();   // previous tile fully consumed (also covers Q fill at t=0)
        #pragma unroll
        for (int i = 0; i < 8; i++) {
            int e = tid + i * 128;
            int kv = e >> 4, dq = (e & 15) << 2;
            *(uint4*)&Kt[kv * LDQ_ + dq] = cvt4(kreg[i]);
            *(uint4*)&Vt[kv * LDV_ + dq] = cvt4(vreg[i]);
        }
        __syncthreads();

        // S = Q K^T (log2 domain)
        float s[2][8][4];
        #pragma unroll
        for (int mb = 0; mb < 2; mb++)
            #pragma unroll
            for (int nt = 0; nt < 8; nt++)
                #pragma unroll
                for (int j = 0; j < 4; j++) s[mb][nt][j] = 0.f;
        #pragma unroll
        for (int ks = 0; ks < 8; ks++) {
            unsigned a0[4], a1[4];
            ldsm4(a0, qAddr0 + ks * 32);
            ldsm4(a1, qAddr1 + ks * 32);
            #pragma unroll
            for (int p = 0; p < 4; p++) {
                unsigned b[4];
                ldsm4(b, kAddr + p * (16 * LDQ_ * 4) + ks * 32);
                mma8(s[0][2 * p],     a0, b);
                mma8(s[0][2 * p + 1], a0, b + 2);
                mma8(s[1][2 * p],     a1, b);
                mma8(s[1][2 * p + 1], a1, b + 2);
            }
        }

        // online softmax (base-2); row slots r = mb*2 + h
        #pragma unroll
        for (int mb = 0; mb < 2; mb++) {
            #pragma unroll
            for (int h = 0; h < 2; h++) {
                const int r = mb * 2 + h;
                float mx = -1e30f;
                #pragma unroll
                for (int nt = 0; nt < 8; nt++)
                    mx = fmaxf(mx, fmaxf(s[mb][nt][2 * h], s[mb][nt][2 * h + 1]));
                mx = fmaxf(mx, __shfl_xor_sync(0xffffffffu, mx, 1));
                mx = fmaxf(mx, __shfl_xor_sync(0xffffffffu, mx, 2));
                float mn = fmaxf(mr[r], mx);
                float alpha = ex2(mr[r] - mn);
                mr[r] = mn;
                float rs = 0.f;
                #pragma unroll
                for (int nt = 0; nt < 8; nt++) {
                    s[mb][nt][2 * h]     = ex2(s[mb][nt][2 * h] - mn);
                    s[mb][nt][2 * h + 1] = ex2(s[mb][nt][2 * h + 1] - mn);
                    rs += s[mb][nt][2 * h] + s[mb][nt][2 * h + 1];
                }
                rs += __shfl_xor_sync(0xffffffffu, rs, 1);
                rs += __shfl_xor_sync(0xffffffffu, rs, 2);
                lr[r] = lr[r] * alpha + rs;
                #pragma unroll
                for (int nt = 0; nt < 8; nt++) {
                    o[mb][nt][2 * h]     *= alpha;
                    o[mb][nt][2 * h + 1] *= alpha;
                }
            }
        }

        // store P (row-major, tf32) — same-warp producer/consumer
        #pragma unroll
        for (int mb = 0; mb < 2; mb++) {
            int pr = warp * 32 + mb * 16 + qr;
            #pragma unroll
            for (int nt = 0; nt < 8; nt++) {
                *(uint2*)&Ps[pr * LDQ_ + nt * 8 + 2 * qc] =
                    make_uint2(f2tf(s[mb][nt][0]), f2tf(s[mb][nt][1]));
                *(uint2*)&Ps[(pr + 8) * LDQ_ + nt * 8 + 2 * qc] =
                    make_uint2(f2tf(s[mb][nt][2]), f2tf(s[mb][nt][3]));
            }
        }
        __syncwarp();

        // O += P V   (V row-major: b0 = V[ks*8+qc][nt*8+qr], bank-injective)
        #pragma unroll
        for (int ks = 0; ks < 8; ks++) {
            unsigned a0[4], a1[4];
            ldsm4(a0, pAddr0 + ks * 32);
            ldsm4(a1, pAddr1 + ks * 32);
            const int vb0 = (ks * 8 + qc) * LDV_ + qr;
            #pragma unroll
            for (int nt = 0; nt < 8; nt++) {
                unsigned b[2];
                b[0] = Vt[vb0 + nt * 8];
                b[1] = Vt[vb0 + 4 * LDV_ + nt * 8];
                mma8(o[0][nt], a0, b);
                mma8(o[1][nt], a1, b);
            }
        }
    }

    // epilogue: normalize and write to g_X
    const int bg = bh >> 3, hg = bh & 7;
    #pragma unroll
    for (int mb = 0; mb < 2; mb++) {
        #pragma unroll
        for (int h = 0; h < 2; h++) {
            const int r = mb * 2 + h;
            float inv = 1.f / lr[r];
            int rowg = n0 + warp * 32 + mb * 16 + h * 8 + qr;
            float* X = &g_X[(bg * N_ + rowg) * C_ + hg * D_];
            #pragma unroll
            for (int nt = 0; nt < 8; nt++) {
                int col = nt * 8 + 2 * qc;
                *(float2*)&X[col] = make_float2(o[mb][nt][2 * h] * inv,
                                                o[mb][nt][2 * h + 1] * inv);
            }
        }
    }
}

// ---------------------------------------------------------------------------
// Output projection: out = X @ Wp^T + bp. Same tiling as proj_qkv.
// ---------------------------------------------------------------------------
__global__ __launch_bounds__(128, 3) void proj_out_kernel(
    const float* __restrict__ Wp, const float* __restrict__ bp,
    float* __restrict__ out)
{
    const int r0 = blockIdx.y * 128;
    const int cb = blockIdx.x * 64;

    __shared__ unsigned Asu[128 * LDP_];
    __shared__ unsigned Wsu[64 * LDP_];

    const int tid  = threadIdx.x;
    const int warp = tid >> 5;
    const int lane = tid & 31;
    const int qr = lane >> 2, qc = lane & 3;
    const int lrow = ((lane >> 3) & 1) * 8 + (lane & 7);
    const int lch  = ((lane >> 4) & 1) * 4;
    const int brow = ((lane >> 4) & 1) * 8 + (lane & 7);
    const int bch  = ((lane >> 3) & 1) * 4;

    const unsigned aAddr0 = su32(&Asu[(warp * 32 + lrow) * LDP_ + lch]);
    const unsigned aAddr1 = su32(&Asu[(warp * 32 + 16 + lrow) * LDP_ + lch]);
    const unsigned wAddr  = su32(&Wsu[brow * LDP_ + bch]);

    float acc[2][8][4];
    #pragma unroll
    for (int mb = 0; mb < 2; mb++)
        #pragma unroll
        for (int nt = 0; nt < 8; nt++)
            #pragma unroll
            for (int j = 0; j < 4; j++) acc[mb][nt][j] = 0.f;

    for (int k0 = 0; k0 < C_; k0 += 32) {
        #pragma unroll
        for (int i = 0; i < 8; i++) {
            int idx = tid + i * 128;
            int row = idx >> 3, kq = (idx & 7) << 2;
            float4 v = *(const float4*)&g_X[(r0 + row) * C_ + k0 + kq];
            *(uint4*)&Asu[row * LDP_ + kq] = cvt4(v);
        }
        #pragma unroll
        for (int i = 0; i < 4; i++) {
            int idx = tid + i * 128;
            int row = idx >> 3, kq = (idx & 7) << 2;
            float4 v = *(const float4*)&Wp[(cb + row) * C_ + k0 + kq];
            *(uint4*)&Wsu[row * LDP_ + kq] = cvt4(v);
        }
        __syncthreads();

        #pragma unroll
        for (int ks = 0; ks < 4; ks++) {
            unsigned a0[4], a1[4];
            ldsm4(a0, aAddr0 + ks * 32);
            ldsm4(a1, aAddr1 + ks * 32);
            #pragma unroll
            for (int p = 0; p < 4; p++) {
                unsigned b[4];
                ldsm4(b, wAddr + p * (16 * LDP_ * 4) + ks * 32);
                mma8(acc[0][2 * p],     a0, b);
                mma8(acc[0][2 * p + 1], a0, b + 2);
                mma8(acc[1][2 * p],     a1, b);
                mma8(acc[1][2 * p + 1], a1, b + 2);
            }
        }
        __syncthreads();
    }

    #pragma unroll
    for (int mb = 0; mb < 2; mb++) {
        int row0 = r0 + warp * 32 + mb * 16 + qr;
        int row1 = row0 + 8;
        #pragma unroll
        for (int nt = 0; nt < 8; nt++) {
            int col = cb + nt * 8 + 2 * qc;
            float b0v = bp[col], b1v = bp[col + 1];
            *(float2*)&out[row0 * C_ + col] =
                make_float2(acc[mb][nt][0] + b0v, acc[mb][nt][1] + b1v);
            *(float2*)&out[row1 * C_ + col] =
                make_float2(acc[mb][nt][2] + b0v, acc[mb][nt][3] + b1v);
        }
    }
}

extern "C" void kernel_launch(void* const* d_in, const int* in_sizes, int n_in,
                              void* d_out, int out_size)
{
    const float* query = (const float*)d_in[0];
    const float* key   = (const float*)d_in[1];
    const float* value = (const float*)d_in[2];
    const float* Wq    = (const float*)d_in[3];
    const float* Wk    = (const float*)d_in[4];
    const float* Wv    = (const float*)d_in[5];
    const float* Wp    = (const float*)d_in[6];
    const float* bp    = (const float*)d_in[7];
    float* out = (float*)d_out;

    const int attn_smem =
        (128 * LDQ_ + 64 * LDQ_ + 64 * LDV_ + 128 * LDQ_) * (int)sizeof(unsigned); // 105472
    cudaFuncSetAttribute(attn_kernel,
                         cudaFuncAttributeMaxDynamicSharedMemorySize, attn_smem);

    dim3 blk(128);
    proj_qkv_kernel<<<dim3(8, 64, 3), blk>>>(query, key, value, Wq, Wk, Wv);
    attn_kernel<<<dim3(32, 16), blk, attn_smem>>>();
    proj_out_kernel<<<dim3(8, 64), blk>>>(Wp, bp, out);
}